// round 2
// baseline (speedup 1.0000x reference)
#include <cuda_runtime.h>
#include <math.h>

// Problem constants
#define BC   4      // new frames
#define LBC  28     // buffered frames
#define MC   32     // total memory frames
#define DKC  256    // key dim
#define DVC  32     // value dim
#define PC   4096   // pixels = 64*64
// softmax groups: (b, m, h) over w=64

// ---------------- scratch (no allocation allowed -> __device__ globals) ----------------
__device__ float g_q   [BC * DKC * PC];  // 16 MB  q[b][e][p]
__device__ float g_k4  [BC * DKC * PC];  // 16 MB  k-proj of fc, frames 0..3
__device__ float g_v4  [BC * DVC * PC];  // 2 MB   v-proj of fm, frames 0..3
__device__ float g_attn[BC * MC  * PC];  // 2 MB   scores -> attn (in-place softmax)

// ---------------------------------------------------------------------------
// Kernel 1: projection GEMM. For each frame b:
//   C[e,p] = sum_d W[d,e] * fc[b,d,p],  W = Q for e-tiles 0..1, K for 2..3.
// Classic 128x128x8 tile, 256 threads, 8x8 micro-tile, float4 everywhere.
// ---------------------------------------------------------------------------
__global__ __launch_bounds__(256) void proj_qk_kernel(
    const float* __restrict__ fc, const float* __restrict__ Qw, const float* __restrict__ Kw)
{
    __shared__ float As[8][128];  // As[k][e] = W[(d0+k)*DKC + e0+e]   (already "transposed")
    __shared__ float Xs[8][128];  // Xs[k][p] = fc[b][(d0+k)][p0+p]

    const int tid = threadIdx.x;
    const int b   = blockIdx.z;
    const int et  = blockIdx.y;           // 0,1 -> Q ; 2,3 -> K
    const int p0  = blockIdx.x * 128;

    const float* W  = (et < 2) ? Qw : Kw;
    const int    e0 = (et & 1) * 128;
    const float* X  = fc + (size_t)b * (DKC * PC);
    float*       Out = ((et < 2) ? g_q : g_k4) + (size_t)b * (DKC * PC)
                       + (size_t)e0 * PC + p0;

    const int lk = tid >> 5;          // 0..7   smem-load row
    const int lx = (tid & 31) * 4;    // 0..124 smem-load col (float4)
    const int tx = (tid & 15) * 4;    // micro-tile p base
    const int ty = (tid >> 4) * 4;    // micro-tile e base

    float acc[8][8];
#pragma unroll
    for (int i = 0; i < 8; ++i)
#pragma unroll
        for (int j = 0; j < 8; ++j) acc[i][j] = 0.f;

    for (int d0 = 0; d0 < DKC; d0 += 8) {
        __syncthreads();
        *(float4*)&As[lk][lx] = *(const float4*)&W[(size_t)(d0 + lk) * DKC + e0 + lx];
        *(float4*)&Xs[lk][lx] = *(const float4*)&X[(size_t)(d0 + lk) * PC  + p0 + lx];
        __syncthreads();
#pragma unroll
        for (int k = 0; k < 8; ++k) {
            float4 a0 = *(const float4*)&As[k][ty];
            float4 a1 = *(const float4*)&As[k][64 + ty];
            float4 x0 = *(const float4*)&Xs[k][tx];
            float4 x1 = *(const float4*)&Xs[k][64 + tx];
            float a[8] = {a0.x, a0.y, a0.z, a0.w, a1.x, a1.y, a1.z, a1.w};
            float x[8] = {x0.x, x0.y, x0.z, x0.w, x1.x, x1.y, x1.z, x1.w};
#pragma unroll
            for (int i = 0; i < 8; ++i)
#pragma unroll
                for (int j = 0; j < 8; ++j)
                    acc[i][j] += a[i] * x[j];
        }
    }

#pragma unroll
    for (int i = 0; i < 8; ++i) {
        const int e = (i < 4) ? (ty + i) : (64 + ty + (i - 4));
        float* o = Out + (size_t)e * PC;
        float4 r0 = make_float4(acc[i][0], acc[i][1], acc[i][2], acc[i][3]);
        float4 r1 = make_float4(acc[i][4], acc[i][5], acc[i][6], acc[i][7]);
        *(float4*)&o[tx]      = r0;
        *(float4*)&o[64 + tx] = r1;
    }
}

// ---------------------------------------------------------------------------
// Kernel 2: v projection.  g_v4[b,e,p] = sum_d fm[b,d,p] * V[d,e]
// thread = (p, b); V cached in smem (broadcast access).
// ---------------------------------------------------------------------------
__global__ __launch_bounds__(128) void proj_v_kernel(
    const float* __restrict__ fm, const float* __restrict__ Vw)
{
    __shared__ float Vs[DVC][DVC];
    const int tid = threadIdx.x;
    for (int i = tid; i < DVC * DVC; i += 128) Vs[i >> 5][i & 31] = Vw[i];
    __syncthreads();

    const int gid = blockIdx.x * 128 + tid;   // 16384 threads
    const int b = gid >> 12;
    const int p = gid & (PC - 1);

    float f[DVC];
    const float* fmp = fm + (size_t)b * DVC * PC + p;
#pragma unroll
    for (int d = 0; d < DVC; ++d) f[d] = fmp[(size_t)d * PC];

    float* vo = g_v4 + (size_t)b * DVC * PC + p;
#pragma unroll 4
    for (int e = 0; e < DVC; ++e) {
        float acc = 0.f;
#pragma unroll
        for (int d = 0; d < DVC; ++d) acc += f[d] * Vs[d][e];
        vo[(size_t)e * PC] = acc;
    }
}

// ---------------------------------------------------------------------------
// Kernel 3: scores.  thread = (pixel p, m-group of 8).
//   S[b][m] = scale * sum_d q[b,d,p] * k[m,d,p]
//   k[m] = g_k4[m] for m<4 else key_buffer[m-4]. Writes to g_attn[b*32+m][p].
// ---------------------------------------------------------------------------
__global__ __launch_bounds__(128) void scores_kernel(
    const float* __restrict__ kbuf, float scale)
{
    const int gid = blockIdx.x * 128 + threadIdx.x;  // 16384 threads
    const int mg  = gid >> 12;                       // 0..3 (group of 8 m's)
    const int p   = gid & (PC - 1);

    const float* qp = g_q + p;
    const float* kp[8];
#pragma unroll
    for (int j = 0; j < 8; ++j) {
        const int m = mg * 8 + j;
        kp[j] = ((m < BC) ? (g_k4 + (size_t)m * DKC * PC)
                          : (kbuf + (size_t)(m - BC) * DKC * PC)) + p;
    }

    float S[4][8];
#pragma unroll
    for (int bb = 0; bb < 4; ++bb)
#pragma unroll
        for (int j = 0; j < 8; ++j) S[bb][j] = 0.f;

#pragma unroll 4
    for (int d = 0; d < DKC; ++d) {
        const float qv0 = qp[(size_t)(0 * DKC + d) * PC];
        const float qv1 = qp[(size_t)(1 * DKC + d) * PC];
        const float qv2 = qp[(size_t)(2 * DKC + d) * PC];
        const float qv3 = qp[(size_t)(3 * DKC + d) * PC];
#pragma unroll
        for (int j = 0; j < 8; ++j) {
            const float kv = kp[j][(size_t)d * PC];
            S[0][j] += qv0 * kv;
            S[1][j] += qv1 * kv;
            S[2][j] += qv2 * kv;
            S[3][j] += qv3 * kv;
        }
    }

#pragma unroll
    for (int bb = 0; bb < 4; ++bb)
#pragma unroll
        for (int j = 0; j < 8; ++j)
            g_attn[(size_t)(bb * MC + mg * 8 + j) * PC + p] = S[bb][j] * scale;
}

// ---------------------------------------------------------------------------
// Kernel 4: softmax over w (last axis), in-place on g_attn.
// One thread per (b,m,h) group of 64 contiguous floats.
// ---------------------------------------------------------------------------
__global__ __launch_bounds__(128) void softmax_kernel()
{
    const int g = blockIdx.x * 128 + threadIdx.x;      // 8192 groups
    float* base = g_attn + (size_t)(g >> 6) * PC + (size_t)(g & 63) * 64;

    float v[64];
#pragma unroll
    for (int i = 0; i < 16; ++i) {
        float4 t = *(const float4*)&base[i * 4];
        v[i*4+0] = t.x; v[i*4+1] = t.y; v[i*4+2] = t.z; v[i*4+3] = t.w;
    }
    float mx = v[0];
#pragma unroll
    for (int i = 1; i < 64; ++i) mx = fmaxf(mx, v[i]);
    float s = 0.f;
#pragma unroll
    for (int i = 0; i < 64; ++i) { v[i] = __expf(v[i] - mx); s += v[i]; }
    const float inv = 1.f / s;
#pragma unroll
    for (int i = 0; i < 16; ++i) {
        float4 t = make_float4(v[i*4]*inv, v[i*4+1]*inv, v[i*4+2]*inv, v[i*4+3]*inv);
        *(float4*)&base[i * 4] = t;
    }
}

// ---------------------------------------------------------------------------
// Kernel 5: ctx + blend.  thread = (p, b).
//   out[b,d,p] = fm[b,d,p] + 0.5 * sum_m attn[b,m,p] * v[m,d,p]
// ---------------------------------------------------------------------------
__global__ __launch_bounds__(128) void ctx_out_kernel(
    const float* __restrict__ vbuf, const float* __restrict__ fm,
    float* __restrict__ out)
{
    const int gid = blockIdx.x * 128 + threadIdx.x;  // 16384 threads
    const int b = gid >> 12;
    const int p = gid & (PC - 1);

    float c[DVC];
#pragma unroll
    for (int d = 0; d < DVC; ++d) c[d] = 0.f;

    const float* ap = g_attn + (size_t)b * MC * PC + p;
#pragma unroll 4
    for (int m = 0; m < MC; ++m) {
        const float a = ap[(size_t)m * PC];
        const float* vp = ((m < BC) ? (g_v4 + (size_t)m * DVC * PC)
                                    : (vbuf + (size_t)(m - BC) * DVC * PC)) + p;
#pragma unroll
        for (int d = 0; d < DVC; ++d) c[d] += a * vp[(size_t)d * PC];
    }

    const float* fmp = fm + (size_t)b * DVC * PC + p;
    float*       op  = out + (size_t)b * DVC * PC + p;
#pragma unroll
    for (int d = 0; d < DVC; ++d)
        op[(size_t)d * PC] = fmp[(size_t)d * PC] + 0.5f * c[d];
}

// ---------------------------------------------------------------------------
extern "C" void kernel_launch(void* const* d_in, const int* in_sizes, int n_in,
                              void* d_out, int out_size)
{
    (void)in_sizes; (void)n_in; (void)out_size;
    const float* fc = (const float*)d_in[0];  // [4,256,64,64]
    const float* fm = (const float*)d_in[1];  // [4,32,64,64]
    const float* kb = (const float*)d_in[2];  // [28,256,64,64]
    const float* vb = (const float*)d_in[3];  // [28,32,64,64]
    const float* Qw = (const float*)d_in[4];  // [256,256]
    const float* Kw = (const float*)d_in[5];  // [256,256]
    const float* Vw = (const float*)d_in[6];  // [32,32]
    float* out = (float*)d_out;               // [4,32,64,64]

    // scale = log(32*64*64 + 64*64, 1000) / sqrt(256)
    const float scale = (float)(log(135168.0) / log(1000.0) / 16.0);

    proj_qk_kernel<<<dim3(32, 4, 4), 256>>>(fc, Qw, Kw);
    proj_v_kernel<<<128, 128>>>(fm, Vw);
    scores_kernel<<<128, 128>>>(kb, scale);
    softmax_kernel<<<64, 128>>>();
    ctx_out_kernel<<<128, 128>>>(vb, fm, out);
}

// round 3
// speedup vs baseline: 1.7448x; 1.7448x over previous
#include <cuda_runtime.h>
#include <cuda_bf16.h>
#include <math.h>
#include <stdint.h>

#define BC   4
#define MC   32
#define DKC  256
#define DVC  32
#define PC   4096

// ---------------- scratch ----------------
__device__ float g_q   [BC * DKC * PC];   // q[b][e][p]
__device__ float g_k4  [BC * DKC * PC];   // k-proj frames 0..3
__device__ float g_v4  [BC * DVC * PC];
__device__ float g_attn[BC * MC  * PC];
__device__ __nv_bfloat16 g_fch[BC * DKC * PC];   // fc hi
__device__ __nv_bfloat16 g_fcl[BC * DKC * PC];   // fc lo
__device__ __nv_bfloat16 g_wh [2 * DKC * DKC];   // [isK][e][d] transposed weights hi
__device__ __nv_bfloat16 g_wl [2 * DKC * DKC];   // lo

// ---------------- PTX helpers ----------------
__device__ __forceinline__ uint32_t smem_u32(const void* p) {
    return (uint32_t)__cvta_generic_to_shared(p);
}
#define CP_ASYNC16(dst, src) \
    asm volatile("cp.async.cg.shared.global [%0], [%1], 16;\n" :: "r"(dst), "l"(src))
#define CP_COMMIT() asm volatile("cp.async.commit_group;\n")
#define CP_WAIT1()  asm volatile("cp.async.wait_group 1;\n")
#define CP_WAIT0()  asm volatile("cp.async.wait_group 0;\n")

#define LDSM_X4(r0,r1,r2,r3,addr) \
    asm volatile("ldmatrix.sync.aligned.m8n8.x4.shared.b16 {%0,%1,%2,%3}, [%4];" \
        : "=r"(r0),"=r"(r1),"=r"(r2),"=r"(r3) : "r"(addr))
#define LDSM_X4_T(r0,r1,r2,r3,addr) \
    asm volatile("ldmatrix.sync.aligned.m8n8.x4.trans.shared.b16 {%0,%1,%2,%3}, [%4];" \
        : "=r"(r0),"=r"(r1),"=r"(r2),"=r"(r3) : "r"(addr))
#define MMA16816(c0,c1,c2,c3,a0,a1,a2,a3,b0,b1) \
    asm volatile("mma.sync.aligned.m16n8k16.row.col.f32.bf16.bf16.f32 " \
        "{%0,%1,%2,%3},{%4,%5,%6,%7},{%8,%9},{%0,%1,%2,%3};" \
        : "+f"(c0),"+f"(c1),"+f"(c2),"+f"(c3) \
        : "r"(a0),"r"(a1),"r"(a2),"r"(a3),"r"(b0),"r"(b1))

// ---------------------------------------------------------------------------
// Convert weights: g_wh/g_wl[isK][e][d] = split(W[d][e]) (transposed for MMA A)
// ---------------------------------------------------------------------------
__global__ __launch_bounds__(256) void convert_w_kernel(
    const float* __restrict__ Qw, const float* __restrict__ Kw)
{
    const int gid = blockIdx.x * 256 + threadIdx.x;        // 65536 threads, 2 d each
    const int isK = gid >> 15;
    const int rem = gid & 32767;
    const int e = rem >> 7;
    const int d = (rem & 127) * 2;
    const float* W = isK ? Kw : Qw;
    float v0 = W[(size_t)d * DKC + e];
    float v1 = W[(size_t)(d + 1) * DKC + e];
    __nv_bfloat16 h0 = __float2bfloat16(v0);
    __nv_bfloat16 h1 = __float2bfloat16(v1);
    __nv_bfloat16 l0 = __float2bfloat16(v0 - __bfloat162float(h0));
    __nv_bfloat16 l1 = __float2bfloat16(v1 - __bfloat162float(h1));
    __nv_bfloat162 hp; hp.x = h0; hp.y = h1;
    __nv_bfloat162 lp; lp.x = l0; lp.y = l1;
    const size_t idx = ((size_t)isK * 65536 + (size_t)e * 256 + d) >> 1;
    ((__nv_bfloat162*)g_wh)[idx] = hp;
    ((__nv_bfloat162*)g_wl)[idx] = lp;
}

// ---------------------------------------------------------------------------
// Convert fc to bf16 hi/lo
// ---------------------------------------------------------------------------
__global__ __launch_bounds__(256) void convert_fc_kernel(const float* __restrict__ fc)
{
    const size_t gid = (size_t)blockIdx.x * 256 + threadIdx.x;  // 1048576 threads x4 elems
    float4 v = ((const float4*)fc)[gid];
    __nv_bfloat16 h[4], l[4];
    float vv[4] = {v.x, v.y, v.z, v.w};
#pragma unroll
    for (int i = 0; i < 4; ++i) {
        h[i] = __float2bfloat16(vv[i]);
        l[i] = __float2bfloat16(vv[i] - __bfloat162float(h[i]));
    }
    __nv_bfloat162 h0; h0.x = h[0]; h0.y = h[1];
    __nv_bfloat162 h1; h1.x = h[2]; h1.y = h[3];
    __nv_bfloat162 l0; l0.x = l[0]; l0.y = l[1];
    __nv_bfloat162 l1; l1.x = l[2]; l1.y = l[3];
    ((__nv_bfloat162*)g_fch)[gid * 2]     = h0;
    ((__nv_bfloat162*)g_fch)[gid * 2 + 1] = h1;
    ((__nv_bfloat162*)g_fcl)[gid * 2]     = l0;
    ((__nv_bfloat162*)g_fcl)[gid * 2 + 1] = l1;
}

// ---------------------------------------------------------------------------
// bf16-split tensor-core GEMM: C[e,p] = sum_d W[d,e] * fc[b,d,p]
// 3 passes: Wh*Xh + Wh*Xl + Wl*Xh. BM=128 BN=128 KC=32, 8 warps (2m x 4n).
// ---------------------------------------------------------------------------
#define A_PAD 40     // 32 + 8 bf16 per row
#define B_PAD 136    // 128 + 8 bf16 per row

__device__ __forceinline__ void gemm_issue(
    int it, __nv_bfloat16* As, __nv_bfloat16* Bs,
    const __nv_bfloat16* Wh, const __nv_bfloat16* Wl,
    const __nv_bfloat16* Xh, const __nv_bfloat16* Xl,
    int e0, int p0, int tid)
{
    const int ph = it >> 3;
    const int d0 = (it & 7) << 5;
    const __nv_bfloat16* Ag = (ph < 2) ? Wh : Wl;
    const __nv_bfloat16* Bg = (ph == 1) ? Xl : Xh;
    const int arow = tid >> 2, ac = (tid & 3) * 8;
    const int brow = tid >> 4, bc = (tid & 15) * 8;
    uint32_t da = smem_u32(&As[arow * A_PAD + ac]);
    const __nv_bfloat16* sa = Ag + (size_t)(e0 + arow) * 256 + d0 + ac;
    CP_ASYNC16(da, sa);
    CP_ASYNC16(da + 64 * A_PAD * 2, sa + 64 * 256);
    uint32_t db = smem_u32(&Bs[brow * B_PAD + bc]);
    const __nv_bfloat16* sb = Bg + (size_t)(d0 + brow) * PC + p0 + bc;
    CP_ASYNC16(db, sb);
    CP_ASYNC16(db + 16 * B_PAD * 2, sb + 16 * PC);
    CP_COMMIT();
}

__global__ __launch_bounds__(256) void gemm_bf16_kernel()
{
    __shared__ __nv_bfloat16 Asm[2][128 * A_PAD];
    __shared__ __nv_bfloat16 Bsm[2][32 * B_PAD];

    const int tid = threadIdx.x;
    const int p0 = blockIdx.x * 128;
    const int y = blockIdx.y;
    const int isK = y >> 1;
    const int e0 = (y & 1) * 128;
    const int b = blockIdx.z;

    const __nv_bfloat16* Wh = g_wh + (size_t)isK * 65536;
    const __nv_bfloat16* Wl = g_wl + (size_t)isK * 65536;
    const __nv_bfloat16* Xh = g_fch + (size_t)b * (DKC * PC);
    const __nv_bfloat16* Xl = g_fcl + (size_t)b * (DKC * PC);
    float* Out = (isK ? g_k4 : g_q) + (size_t)b * (DKC * PC);

    const int lane = tid & 31, wid = tid >> 5;
    const int ew = (wid >> 2) * 64;   // warp m offset
    const int pw = (wid & 3) * 32;    // warp n offset

    float acc[4][4][4];
#pragma unroll
    for (int mt = 0; mt < 4; ++mt)
#pragma unroll
        for (int nt = 0; nt < 4; ++nt)
#pragma unroll
            for (int i = 0; i < 4; ++i) acc[mt][nt][i] = 0.f;

    gemm_issue(0, Asm[0], Bsm[0], Wh, Wl, Xh, Xl, e0, p0, tid);

    for (int it = 0; it < 24; ++it) {
        const int st = it & 1;
        if (it < 23) {
            gemm_issue(it + 1, Asm[st ^ 1], Bsm[st ^ 1], Wh, Wl, Xh, Xl, e0, p0, tid);
            CP_WAIT1();
        } else {
            CP_WAIT0();
        }
        __syncthreads();

        __nv_bfloat16* As = Asm[st];
        __nv_bfloat16* Bs = Bsm[st];
#pragma unroll
        for (int ks = 0; ks < 2; ++ks) {
            const int k16 = ks * 16;
            uint32_t af[4][4], bfr[2][4];
#pragma unroll
            for (int mt = 0; mt < 4; ++mt) {
                uint32_t ad = smem_u32(&As[(ew + mt * 16 + (lane & 15)) * A_PAD
                                           + k16 + (lane >> 4) * 8]);
                LDSM_X4(af[mt][0], af[mt][1], af[mt][2], af[mt][3], ad);
            }
#pragma unroll
            for (int n2 = 0; n2 < 2; ++n2) {
                uint32_t bd = smem_u32(&Bs[(k16 + (lane & 15)) * B_PAD
                                           + pw + n2 * 16 + (lane >> 4) * 8]);
                LDSM_X4_T(bfr[n2][0], bfr[n2][1], bfr[n2][2], bfr[n2][3], bd);
            }
#pragma unroll
            for (int mt = 0; mt < 4; ++mt)
#pragma unroll
                for (int nt = 0; nt < 4; ++nt)
                    MMA16816(acc[mt][nt][0], acc[mt][nt][1], acc[mt][nt][2], acc[mt][nt][3],
                             af[mt][0], af[mt][1], af[mt][2], af[mt][3],
                             bfr[nt >> 1][(nt & 1) * 2], bfr[nt >> 1][(nt & 1) * 2 + 1]);
        }
        __syncthreads();
    }

    // epilogue
#pragma unroll
    for (int mt = 0; mt < 4; ++mt) {
#pragma unroll
        for (int nt = 0; nt < 4; ++nt) {
            const int r = e0 + ew + mt * 16 + (lane >> 2);
            const int c = p0 + pw + nt * 8 + (lane & 3) * 2;
            float2 v0 = make_float2(acc[mt][nt][0], acc[mt][nt][1]);
            float2 v1 = make_float2(acc[mt][nt][2], acc[mt][nt][3]);
            *(float2*)&Out[(size_t)r * PC + c] = v0;
            *(float2*)&Out[(size_t)(r + 8) * PC + c] = v1;
        }
    }
}

// ---------------------------------------------------------------------------
// v projection (unchanged)
// ---------------------------------------------------------------------------
__global__ __launch_bounds__(128) void proj_v_kernel(
    const float* __restrict__ fm, const float* __restrict__ Vw)
{
    __shared__ float Vs[DVC][DVC];
    const int tid = threadIdx.x;
    for (int i = tid; i < DVC * DVC; i += 128) Vs[i >> 5][i & 31] = Vw[i];
    __syncthreads();

    const int gid = blockIdx.x * 128 + tid;
    const int b = gid >> 12;
    const int p = gid & (PC - 1);

    float f[DVC];
    const float* fmp = fm + (size_t)b * DVC * PC + p;
#pragma unroll
    for (int d = 0; d < DVC; ++d) f[d] = fmp[(size_t)d * PC];

    float* vo = g_v4 + (size_t)b * DVC * PC + p;
#pragma unroll 4
    for (int e = 0; e < DVC; ++e) {
        float a = 0.f;
#pragma unroll
        for (int d = 0; d < DVC; ++d) a += f[d] * Vs[d][e];
        vo[(size_t)e * PC] = a;
    }
}

// ---------------------------------------------------------------------------
// scores + softmax fused. Block = (h-row of 64 w) x (m-tile of 8). All 4 b.
// 256 threads = 64 w x 4 m-groups (2 m each).
// ---------------------------------------------------------------------------
__global__ __launch_bounds__(256) void scores_softmax_kernel(
    const float* __restrict__ kbuf, float scale)
{
    __shared__ float sS[4][8][64];
    __shared__ float sMx[4][8], sInv[4][8];

    const int tid = threadIdx.x;
    const int h = blockIdx.x;
    const int mt = blockIdx.y;
    const int w = tid & 63;
    const int mg = tid >> 6;
    const int p = h * 64 + w;
    const int m0 = mt * 8 + mg * 2;

    const float* qp = g_q + p;
    const float* k0 = ((m0 < BC) ? g_k4 + (size_t)m0 * (DKC * PC)
                                 : kbuf + (size_t)(m0 - BC) * (DKC * PC)) + p;
    const float* k1 = ((m0 + 1 < BC) ? g_k4 + (size_t)(m0 + 1) * (DKC * PC)
                                     : kbuf + (size_t)(m0 + 1 - BC) * (DKC * PC)) + p;

    float S[4][2];
#pragma unroll
    for (int bb = 0; bb < 4; ++bb) { S[bb][0] = 0.f; S[bb][1] = 0.f; }

#pragma unroll 4
    for (int d = 0; d < DKC; ++d) {
        const float kv0 = k0[(size_t)d * PC];
        const float kv1 = k1[(size_t)d * PC];
#pragma unroll
        for (int bb = 0; bb < 4; ++bb) {
            const float qv = qp[(size_t)(bb * DKC + d) * PC];
            S[bb][0] += qv * kv0;
            S[bb][1] += qv * kv1;
        }
    }

#pragma unroll
    for (int bb = 0; bb < 4; ++bb) {
        sS[bb][mg * 2][w]     = S[bb][0] * scale;
        sS[bb][mg * 2 + 1][w] = S[bb][1] * scale;
    }
    __syncthreads();

    // reduction: 32 groups (4b x 8m), 8 threads each
    {
        const int g = tid >> 3, j = tid & 7;
        const int bb = g >> 3, ml = g & 7;
        float v[8];
#pragma unroll
        for (int i = 0; i < 8; ++i) v[i] = sS[bb][ml][j * 8 + i];
        float mx = v[0];
#pragma unroll
        for (int i = 1; i < 8; ++i) mx = fmaxf(mx, v[i]);
#pragma unroll
        for (int s = 1; s < 8; s <<= 1) mx = fmaxf(mx, __shfl_xor_sync(0xffffffffu, mx, s));
        float sum = 0.f;
#pragma unroll
        for (int i = 0; i < 8; ++i) sum += __expf(v[i] - mx);
#pragma unroll
        for (int s = 1; s < 8; s <<= 1) sum += __shfl_xor_sync(0xffffffffu, sum, s);
        if (j == 0) { sMx[bb][ml] = mx; sInv[bb][ml] = 1.f / sum; }
    }
    __syncthreads();

#pragma unroll
    for (int bb = 0; bb < 4; ++bb) {
#pragma unroll
        for (int jj = 0; jj < 2; ++jj) {
            const int ml = mg * 2 + jj;
            const float a = __expf(S[bb][jj] * scale - sMx[bb][ml]) * sInv[bb][ml];
            g_attn[((size_t)bb * MC + mt * 8 + ml) * PC + p] = a;
        }
    }
}

// ---------------------------------------------------------------------------
// ctx + blend. thread = (p, d); all 4 b in registers.
// ---------------------------------------------------------------------------
__global__ __launch_bounds__(256) void ctx_out_kernel(
    const float* __restrict__ vbuf, const float* __restrict__ fm,
    float* __restrict__ out)
{
    const int gid = blockIdx.x * 256 + threadIdx.x;   // 131072 threads
    const int d = gid >> 12;
    const int p = gid & (PC - 1);

    float c[4] = {0.f, 0.f, 0.f, 0.f};
    const float* ap = g_attn + p;

#pragma unroll 4
    for (int m = 0; m < MC; ++m) {
        const float* vsrc = (m < BC) ? (g_v4 + (size_t)m * DVC * PC)
                                     : (vbuf + (size_t)(m - BC) * DVC * PC);
        const float vv = vsrc[(size_t)d * PC + p];
#pragma unroll
        for (int bb = 0; bb < 4; ++bb)
            c[bb] += ap[(size_t)(bb * MC + m) * PC] * vv;
    }

#pragma unroll
    for (int bb = 0; bb < 4; ++bb) {
        const size_t o = ((size_t)bb * DVC + d) * PC + p;
        out[o] = fm[o] + 0.5f * c[bb];
    }
}

// ---------------------------------------------------------------------------
extern "C" void kernel_launch(void* const* d_in, const int* in_sizes, int n_in,
                              void* d_out, int out_size)
{
    (void)in_sizes; (void)n_in; (void)out_size;
    const float* fc = (const float*)d_in[0];
    const float* fm = (const float*)d_in[1];
    const float* kb = (const float*)d_in[2];
    const float* vb = (const float*)d_in[3];
    const float* Qw = (const float*)d_in[4];
    const float* Kw = (const float*)d_in[5];
    const float* Vw = (const float*)d_in[6];
    float* out = (float*)d_out;

    const float scale = (float)(log(135168.0) / log(1000.0) / 16.0);

    convert_w_kernel<<<256, 256>>>(Qw, Kw);
    convert_fc_kernel<<<4096, 256>>>(fc);
    gemm_bf16_kernel<<<dim3(32, 4, 4), 256>>>();
    proj_v_kernel<<<128, 128>>>(fm, Vw);
    scores_softmax_kernel<<<dim3(64, 4), 256>>>(kb, scale);
    ctx_out_kernel<<<512, 256>>>(vb, fm, out);
}

// round 8
// speedup vs baseline: 2.9227x; 1.6751x over previous
#include <cuda_runtime.h>
#include <cuda_bf16.h>
#include <math.h>
#include <stdint.h>

#define BC   4
#define MC   32
#define DKC  256
#define DVC  32
#define PC   4096

// ---------------- scratch ----------------
__device__ float g_q   [BC * DKC * PC];
__device__ float g_k4  [BC * DKC * PC];
__device__ float g_v4  [BC * DVC * PC];
__device__ float g_attn[BC * MC  * PC];
__device__ __nv_bfloat16 g_fch[BC * DKC * PC];
__device__ __nv_bfloat16 g_fcl[BC * DKC * PC];
__device__ __nv_bfloat16 g_wh [2 * DKC * DKC];   // [isK][e][d]
__device__ __nv_bfloat16 g_wl [2 * DKC * DKC];

// ---------------- PTX helpers ----------------
__device__ __forceinline__ uint32_t smem_u32(const void* p) {
    return (uint32_t)__cvta_generic_to_shared(p);
}
#define CP_ASYNC16(dst, src) \
    asm volatile("cp.async.cg.shared.global [%0], [%1], 16;\n" :: "r"(dst), "l"(src))
#define CP_COMMIT() asm volatile("cp.async.commit_group;\n")
#define CP_WAIT2()  asm volatile("cp.async.wait_group 2;\n" ::: "memory")
#define CP_WAIT1()  asm volatile("cp.async.wait_group 1;\n" ::: "memory")
#define CP_WAIT0()  asm volatile("cp.async.wait_group 0;\n" ::: "memory")

#define LDSM_X4(r0,r1,r2,r3,addr) \
    asm volatile("ldmatrix.sync.aligned.m8n8.x4.shared.b16 {%0,%1,%2,%3}, [%4];" \
        : "=r"(r0),"=r"(r1),"=r"(r2),"=r"(r3) : "r"(addr))
#define LDSM_X4_T(r0,r1,r2,r3,addr) \
    asm volatile("ldmatrix.sync.aligned.m8n8.x4.trans.shared.b16 {%0,%1,%2,%3}, [%4];" \
        : "=r"(r0),"=r"(r1),"=r"(r2),"=r"(r3) : "r"(addr))
#define MMA16816(c0,c1,c2,c3,a0,a1,a2,a3,b0,b1) \
    asm volatile("mma.sync.aligned.m16n8k16.row.col.f32.bf16.bf16.f32 " \
        "{%0,%1,%2,%3},{%4,%5,%6,%7},{%8,%9},{%0,%1,%2,%3};" \
        : "+f"(c0),"+f"(c1),"+f"(c2),"+f"(c3) \
        : "r"(a0),"r"(a1),"r"(a2),"r"(a3),"r"(b0),"r"(b1))

// ---------------------------------------------------------------------------
// convert weights: g_wh/g_wl[isK][e][d] = split(W[d][e])
// ---------------------------------------------------------------------------
__global__ __launch_bounds__(256) void convert_w_kernel(
    const float* __restrict__ Qw, const float* __restrict__ Kw)
{
    const int gid = blockIdx.x * 256 + threadIdx.x;
    const int isK = gid >> 15;
    const int rem = gid & 32767;
    const int e = rem >> 7;
    const int d = (rem & 127) * 2;
    const float* W = isK ? Kw : Qw;
    float v0 = W[(size_t)d * DKC + e];
    float v1 = W[(size_t)(d + 1) * DKC + e];
    __nv_bfloat16 h0 = __float2bfloat16(v0);
    __nv_bfloat16 h1 = __float2bfloat16(v1);
    __nv_bfloat16 l0 = __float2bfloat16(v0 - __bfloat162float(h0));
    __nv_bfloat16 l1 = __float2bfloat16(v1 - __bfloat162float(h1));
    __nv_bfloat162 hp; hp.x = h0; hp.y = h1;
    __nv_bfloat162 lp; lp.x = l0; lp.y = l1;
    const size_t idx = ((size_t)isK * 65536 + (size_t)e * 256 + d) >> 1;
    ((__nv_bfloat162*)g_wh)[idx] = hp;
    ((__nv_bfloat162*)g_wl)[idx] = lp;
}

__global__ __launch_bounds__(256) void convert_fc_kernel(const float* __restrict__ fc)
{
    const size_t gid = (size_t)blockIdx.x * 256 + threadIdx.x;
    float4 v = ((const float4*)fc)[gid];
    __nv_bfloat16 h[4], l[4];
    float vv[4] = {v.x, v.y, v.z, v.w};
#pragma unroll
    for (int i = 0; i < 4; ++i) {
        h[i] = __float2bfloat16(vv[i]);
        l[i] = __float2bfloat16(vv[i] - __bfloat162float(h[i]));
    }
    __nv_bfloat162 h0; h0.x = h[0]; h0.y = h[1];
    __nv_bfloat162 h1; h1.x = h[2]; h1.y = h[3];
    __nv_bfloat162 l0; l0.x = l[0]; l0.y = l[1];
    __nv_bfloat162 l1; l1.x = l[2]; l1.y = l[3];
    ((__nv_bfloat162*)g_fch)[gid * 2]     = h0;
    ((__nv_bfloat162*)g_fch)[gid * 2 + 1] = h1;
    ((__nv_bfloat162*)g_fcl)[gid * 2]     = l0;
    ((__nv_bfloat162*)g_fcl)[gid * 2 + 1] = l1;
}

// ---------------------------------------------------------------------------
// multistage mma.sync GEMM: Out[e,p] = sum_d W[d,e]*X[d,p], 3 bf16 hi/lo
// passes fused as virtual K=768. BM=128, BN=256, BK=64, 3-stage cp.async.
// 8 warps, warp tile 64x64 (m16n8k16).
// ---------------------------------------------------------------------------
#define AROW 72                      // 64 + 8 pad (bf16)
#define BROW 264                     // 256 + 8 pad (bf16)
#define A_STAGE (128 * AROW)
#define B_STAGE (64 * BROW)
#define STAGE_ELEMS (A_STAGE + B_STAGE)
#define GEMM_SMEM_BYTES (3 * STAGE_ELEMS * 2)

__device__ __forceinline__ void gemm_load_stage(
    __nv_bfloat16* stg, int s, int tid, int isK, int e0, int b, int p0)
{
    const int pass = s >> 2, kc = s & 3, d0 = kc * 64;
    const __nv_bfloat16* Ag = ((pass < 2) ? g_wh : g_wl)
        + (size_t)isK * 65536 + (size_t)e0 * 256 + d0;
    const __nv_bfloat16* Bg = ((pass == 1) ? g_fcl : g_fch)
        + (size_t)b * (DKC * PC) + (size_t)d0 * PC + p0;
    __nv_bfloat16* As = stg;
    __nv_bfloat16* Bs = stg + A_STAGE;
#pragma unroll
    for (int i = 0; i < 4; ++i) {                 // A: 1024 16B chunks
        const int c = tid + i * 256;
        const int row = c >> 3, col = c & 7;      // 128 rows x 8 chunks
        CP_ASYNC16(smem_u32(&As[row * AROW + col * 8]),
                   Ag + (size_t)row * 256 + col * 8);
    }
#pragma unroll
    for (int i = 0; i < 8; ++i) {                 // B: 2048 16B chunks
        const int c = tid + i * 256;
        const int row = c >> 5, col = c & 31;     // 64 rows x 32 chunks
        CP_ASYNC16(smem_u32(&Bs[row * BROW + col * 8]),
                   Bg + (size_t)row * PC + col * 8);
    }
    CP_COMMIT();
}

__global__ void __launch_bounds__(256) gemm_hmma_kernel()
{
    extern __shared__ __nv_bfloat16 sm[];
    const int tid = threadIdx.x, wid = tid >> 5, lane = tid & 31;
    const int p0 = blockIdx.x * 256;
    const int y = blockIdx.y;
    const int isK = y >> 1;
    const int e0 = (y & 1) * 128;
    const int b = blockIdx.z;

    const int ew = (wid >> 2) * 64;   // warp e offset (0/64)
    const int pw = (wid & 3) * 64;    // warp p offset (0..192)

    float acc[4][8][4];
#pragma unroll
    for (int mt = 0; mt < 4; ++mt)
#pragma unroll
        for (int nt = 0; nt < 8; ++nt)
#pragma unroll
            for (int i = 0; i < 4; ++i) acc[mt][nt][i] = 0.f;

    gemm_load_stage(sm, 0, tid, isK, e0, b, p0);
    gemm_load_stage(sm + STAGE_ELEMS, 1, tid, isK, e0, b, p0);
    gemm_load_stage(sm + 2 * STAGE_ELEMS, 2, tid, isK, e0, b, p0);

#pragma unroll 1
    for (int s = 0; s < 12; ++s) {
        if (s < 10)      { CP_WAIT2(); }
        else if (s == 10){ CP_WAIT1(); }
        else             { CP_WAIT0(); }
        __syncthreads();

        __nv_bfloat16* As = sm + (s % 3) * STAGE_ELEMS;
        __nv_bfloat16* Bs = As + A_STAGE;

#pragma unroll
        for (int ks = 0; ks < 4; ++ks) {
            const int k16 = ks * 16;
            uint32_t a[4][4];
#pragma unroll
            for (int mt = 0; mt < 4; ++mt) {
                uint32_t ad = smem_u32(&As[(ew + mt * 16 + (lane & 15)) * AROW
                                           + k16 + (lane >> 4) * 8]);
                LDSM_X4(a[mt][0], a[mt][1], a[mt][2], a[mt][3], ad);
            }
#pragma unroll
            for (int n2 = 0; n2 < 4; ++n2) {
                uint32_t bf[4];
                uint32_t bd = smem_u32(&Bs[(k16 + (lane & 15)) * BROW
                                           + pw + n2 * 16 + (lane >> 4) * 8]);
                LDSM_X4_T(bf[0], bf[1], bf[2], bf[3], bd);
#pragma unroll
                for (int mt = 0; mt < 4; ++mt) {
                    MMA16816(acc[mt][n2*2][0], acc[mt][n2*2][1],
                             acc[mt][n2*2][2], acc[mt][n2*2][3],
                             a[mt][0], a[mt][1], a[mt][2], a[mt][3],
                             bf[0], bf[1]);
                    MMA16816(acc[mt][n2*2+1][0], acc[mt][n2*2+1][1],
                             acc[mt][n2*2+1][2], acc[mt][n2*2+1][3],
                             a[mt][0], a[mt][1], a[mt][2], a[mt][3],
                             bf[2], bf[3]);
                }
            }
        }
        __syncthreads();
        if (s + 3 < 12)
            gemm_load_stage(sm + ((s + 3) % 3) * STAGE_ELEMS, s + 3, tid, isK, e0, b, p0);
    }

    float* Out = (isK ? g_k4 : g_q) + (size_t)b * (DKC * PC);
#pragma unroll
    for (int mt = 0; mt < 4; ++mt) {
#pragma unroll
        for (int nt = 0; nt < 8; ++nt) {
            const int r = e0 + ew + mt * 16 + (lane >> 2);
            const int c = p0 + pw + nt * 8 + (lane & 3) * 2;
            *(float2*)&Out[(size_t)r * PC + c] =
                make_float2(acc[mt][nt][0], acc[mt][nt][1]);
            *(float2*)&Out[(size_t)(r + 8) * PC + c] =
                make_float2(acc[mt][nt][2], acc[mt][nt][3]);
        }
    }
}

// ---------------------------------------------------------------------------
// v projection
// ---------------------------------------------------------------------------
__global__ __launch_bounds__(256) void proj_v_kernel(
    const float* __restrict__ fm, const float* __restrict__ Vw)
{
    __shared__ float Vs[DVC][DVC];
    const int tid = threadIdx.x;
    for (int i = tid; i < DVC * DVC; i += 256) Vs[i >> 5][i & 31] = Vw[i];
    __syncthreads();

    const int gid = blockIdx.x * 256 + tid;   // 65536 threads
    const int eg = gid >> 14;
    const int b = (gid >> 12) & 3;
    const int p = gid & (PC - 1);

    float f[DVC];
    const float* fmp = fm + (size_t)b * DVC * PC + p;
#pragma unroll
    for (int d = 0; d < DVC; ++d) f[d] = fmp[(size_t)d * PC];

    float* vo = g_v4 + (size_t)b * DVC * PC + p;
#pragma unroll
    for (int ee = 0; ee < 8; ++ee) {
        const int e = eg * 8 + ee;
        float a = 0.f;
#pragma unroll
        for (int d = 0; d < DVC; ++d) a += f[d] * Vs[d][e];
        vo[(size_t)e * PC] = a;
    }
}

// ---------------------------------------------------------------------------
// scores + softmax fused, q staged in smem.
// grid (64 h, 2 m-halves), 256 threads = (w 64, mg 4); each mg: 4 m, 4 b.
// ---------------------------------------------------------------------------
__global__ __launch_bounds__(256) void scores_softmax_kernel(
    const float* __restrict__ kbuf, float scale)
{
    __shared__ float qs[32 * 4 * 64];    // [d'][b][w]
    __shared__ float sS[4 * 16 * 64];    // [b][m][w]
    __shared__ float sMx[64], sInv[64];

    const int tid = threadIdx.x;
    const int h = blockIdx.x;
    const int mhalf = blockIdx.y;
    const int w = tid & 63;
    const int mg = tid >> 6;
    const int p = h * 64 + w;

    const float* kp[4];
#pragma unroll
    for (int j = 0; j < 4; ++j) {
        const int m = mhalf * 16 + mg * 4 + j;
        kp[j] = ((m < BC) ? g_k4 + (size_t)m * (DKC * PC)
                          : kbuf + (size_t)(m - BC) * (DKC * PC)) + p;
    }

    float S[4][4];
#pragma unroll
    for (int bb = 0; bb < 4; ++bb)
#pragma unroll
        for (int j = 0; j < 4; ++j) S[bb][j] = 0.f;

    for (int dc = 0; dc < 8; ++dc) {
        __syncthreads();
#pragma unroll
        for (int i = 0; i < 8; ++i) {
            const int flat = (i * 256 + tid) * 4;
            const int d_ = flat >> 8, bb = (flat >> 6) & 3, w0 = flat & 63;
            *(float4*)&qs[flat] = *(const float4*)&g_q[
                ((size_t)(bb * DKC + dc * 32 + d_)) * PC + h * 64 + w0];
        }
        __syncthreads();
#pragma unroll 4
        for (int d_ = 0; d_ < 32; ++d_) {
            float kv[4];
#pragma unroll
            for (int j = 0; j < 4; ++j) kv[j] = kp[j][(size_t)(dc * 32 + d_) * PC];
#pragma unroll
            for (int bb = 0; bb < 4; ++bb) {
                const float qv = qs[(d_ * 4 + bb) * 64 + w];
#pragma unroll
                for (int j = 0; j < 4; ++j) S[bb][j] += qv * kv[j];
            }
        }
    }

#pragma unroll
    for (int bb = 0; bb < 4; ++bb)
#pragma unroll
        for (int j = 0; j < 4; ++j)
            sS[((bb * 16) + mg * 4 + j) * 64 + w] = S[bb][j] * scale;
    __syncthreads();

    {
        const int g = tid >> 2, jj = tid & 3;
        float v[16];
        float mx = -1e30f;
#pragma unroll
        for (int i = 0; i < 16; ++i) { v[i] = sS[g * 64 + jj * 16 + i]; mx = fmaxf(mx, v[i]); }
        mx = fmaxf(mx, __shfl_xor_sync(0xffffffffu, mx, 1));
        mx = fmaxf(mx, __shfl_xor_sync(0xffffffffu, mx, 2));
        float sm = 0.f;
#pragma unroll
        for (int i = 0; i < 16; ++i) sm += __expf(v[i] - mx);
        sm += __shfl_xor_sync(0xffffffffu, sm, 1);
        sm += __shfl_xor_sync(0xffffffffu, sm, 2);
        if (jj == 0) { sMx[g] = mx; sInv[g] = 1.f / sm; }
    }
    __syncthreads();

#pragma unroll
    for (int bb = 0; bb < 4; ++bb)
#pragma unroll
        for (int j = 0; j < 4; ++j) {
            const int g = bb * 16 + mg * 4 + j;
            const float a = __expf(S[bb][j] * scale - sMx[g]) * sInv[g];
            g_attn[((size_t)bb * MC + mhalf * 16 + mg * 4 + j) * PC + p] = a;
        }
}

// ---------------------------------------------------------------------------
// ctx + blend
// ---------------------------------------------------------------------------
__global__ __launch_bounds__(256) void ctx_out_kernel(
    const float* __restrict__ vbuf, const float* __restrict__ fm,
    float* __restrict__ out)
{
    const int gid = blockIdx.x * 256 + threadIdx.x;
    const int d = gid >> 12;
    const int p = gid & (PC - 1);

    float c[4] = {0.f, 0.f, 0.f, 0.f};
    const float* ap = g_attn + p;

#pragma unroll 4
    for (int m = 0; m < MC; ++m) {
        const float* vsrc = (m < BC) ? (g_v4 + (size_t)m * DVC * PC)
                                     : (vbuf + (size_t)(m - BC) * DVC * PC);
        const float vv = vsrc[(size_t)d * PC + p];
#pragma unroll
        for (int bb = 0; bb < 4; ++bb)
            c[bb] += ap[(size_t)(bb * MC + m) * PC] * vv;
    }

#pragma unroll
    for (int bb = 0; bb < 4; ++bb) {
        const size_t o = ((size_t)bb * DVC + d) * PC + p;
        out[o] = fm[o] + 0.5f * c[bb];
    }
}

// ---------------------------------------------------------------------------
extern "C" void kernel_launch(void* const* d_in, const int* in_sizes, int n_in,
                              void* d_out, int out_size)
{
    (void)in_sizes; (void)n_in; (void)out_size;
    const float* fc = (const float*)d_in[0];
    const float* fm = (const float*)d_in[1];
    const float* kb = (const float*)d_in[2];
    const float* vb = (const float*)d_in[3];
    const float* Qw = (const float*)d_in[4];
    const float* Kw = (const float*)d_in[5];
    const float* Vw = (const float*)d_in[6];
    float* out = (float*)d_out;

    const float scale = (float)(log(135168.0) / log(1000.0) / 16.0);

    cudaFuncSetAttribute(gemm_hmma_kernel,
                         cudaFuncAttributeMaxDynamicSharedMemorySize,
                         GEMM_SMEM_BYTES);

    convert_w_kernel<<<256, 256>>>(Qw, Kw);
    convert_fc_kernel<<<4096, 256>>>(fc);
    gemm_hmma_kernel<<<dim3(16, 4, 4), 256, GEMM_SMEM_BYTES>>>();
    proj_v_kernel<<<256, 256>>>(fm, Vw);
    scores_softmax_kernel<<<dim3(64, 2), 256>>>(kb, scale);
    ctx_out_kernel<<<512, 256>>>(vb, fm, out);
}

// round 9
// speedup vs baseline: 3.7326x; 1.2771x over previous
#include <cuda_runtime.h>
#include <cuda_fp16.h>
#include <math.h>
#include <stdint.h>

#define BC   4
#define MC   32
#define DKC  256
#define DVC  32
#define PC   4096

// ---------------- scratch ----------------
__device__ float  g_q   [BC * DKC * PC];
__device__ float  g_k4  [BC * DKC * PC];
__device__ float  g_v4  [BC * DVC * PC];
__device__ float  g_attn[BC * MC  * PC];
__device__ __half g_f16 [BC * DKC * PC];      // fc as fp16
__device__ __half g_w16 [2 * DKC * DKC];      // [isK][e][d] transposed weights fp16

// ---------------- PTX helpers ----------------
__device__ __forceinline__ uint32_t smem_u32(const void* p) {
    return (uint32_t)__cvta_generic_to_shared(p);
}
#define CP_ASYNC16(dst, src) \
    asm volatile("cp.async.cg.shared.global [%0], [%1], 16;\n" :: "r"(dst), "l"(src))
#define CP_COMMIT() asm volatile("cp.async.commit_group;\n")
#define CP_WAITN(n) asm volatile("cp.async.wait_group %0;\n" :: "n"(n) : "memory")

#define LDSM_X4(r0,r1,r2,r3,addr) \
    asm volatile("ldmatrix.sync.aligned.m8n8.x4.shared.b16 {%0,%1,%2,%3}, [%4];" \
        : "=r"(r0),"=r"(r1),"=r"(r2),"=r"(r3) : "r"(addr))
#define LDSM_X4_T(r0,r1,r2,r3,addr) \
    asm volatile("ldmatrix.sync.aligned.m8n8.x4.trans.shared.b16 {%0,%1,%2,%3}, [%4];" \
        : "=r"(r0),"=r"(r1),"=r"(r2),"=r"(r3) : "r"(addr))
#define MMA16816(c0,c1,c2,c3,a0,a1,a2,a3,b0,b1) \
    asm volatile("mma.sync.aligned.m16n8k16.row.col.f32.f16.f16.f32 " \
        "{%0,%1,%2,%3},{%4,%5,%6,%7},{%8,%9},{%0,%1,%2,%3};" \
        : "+f"(c0),"+f"(c1),"+f"(c2),"+f"(c3) \
        : "r"(a0),"r"(a1),"r"(a2),"r"(a3),"r"(b0),"r"(b1))

// ---------------------------------------------------------------------------
// convert weights: g_w16[isK][e][d] = (fp16) W[d][e]
// ---------------------------------------------------------------------------
__global__ __launch_bounds__(256) void convert_w_kernel(
    const float* __restrict__ Qw, const float* __restrict__ Kw)
{
    const int gid = blockIdx.x * 256 + threadIdx.x;   // 65536 threads, 2 d each
    const int isK = gid >> 15;
    const int rem = gid & 32767;
    const int e = rem >> 7;
    const int d = (rem & 127) * 2;
    const float* W = isK ? Kw : Qw;
    __half2 h;
    h.x = __float2half_rn(W[(size_t)d * DKC + e]);
    h.y = __float2half_rn(W[(size_t)(d + 1) * DKC + e]);
    ((__half2*)g_w16)[((size_t)isK * 65536 + (size_t)e * 256 + d) >> 1] = h;
}

// ---------------------------------------------------------------------------
// convert fc to fp16
// ---------------------------------------------------------------------------
__global__ __launch_bounds__(256) void convert_fc_kernel(const float* __restrict__ fc)
{
    const size_t gid = (size_t)blockIdx.x * 256 + threadIdx.x;  // 1048576 threads x4
    float4 v = ((const float4*)fc)[gid];
    __half2 h0, h1;
    h0.x = __float2half_rn(v.x); h0.y = __float2half_rn(v.y);
    h1.x = __float2half_rn(v.z); h1.y = __float2half_rn(v.w);
    ((__half2*)g_f16)[gid * 2]     = h0;
    ((__half2*)g_f16)[gid * 2 + 1] = h1;
}

// ---------------------------------------------------------------------------
// fp16 HMMA GEMM: Out[e,p] = sum_d W[d,e] * X[d,p].
// BM=128, BN=256, BK=64, 4-stage full prefetch. 8 warps, warp tile 64x64.
// ---------------------------------------------------------------------------
#define AROW 72                      // 64 + 8 pad (half)
#define BROW 264                     // 256 + 8 pad (half)
#define A_STAGE (128 * AROW)
#define B_STAGE (64 * BROW)
#define STAGE_ELEMS (A_STAGE + B_STAGE)
#define GEMM_SMEM_BYTES (4 * STAGE_ELEMS * 2)

__device__ __forceinline__ void gemm_load_stage(
    __half* stg, int s, int tid, int isK, int e0, int b, int p0)
{
    const int d0 = s * 64;
    const __half* Ag = g_w16 + (size_t)isK * 65536 + (size_t)e0 * 256 + d0;
    const __half* Bg = g_f16 + (size_t)b * (DKC * PC) + (size_t)d0 * PC + p0;
    __half* As = stg;
    __half* Bs = stg + A_STAGE;
#pragma unroll
    for (int i = 0; i < 4; ++i) {                 // A: 1024 16B chunks
        const int c = tid + i * 256;
        const int row = c >> 3, col = c & 7;      // 128 rows x 8 chunks
        CP_ASYNC16(smem_u32(&As[row * AROW + col * 8]),
                   Ag + (size_t)row * 256 + col * 8);
    }
#pragma unroll
    for (int i = 0; i < 8; ++i) {                 // B: 2048 16B chunks
        const int c = tid + i * 256;
        const int row = c >> 5, col = c & 31;     // 64 rows x 32 chunks
        CP_ASYNC16(smem_u32(&Bs[row * BROW + col * 8]),
                   Bg + (size_t)row * PC + col * 8);
    }
    CP_COMMIT();
}

__global__ void __launch_bounds__(256) gemm_hmma_kernel()
{
    extern __shared__ __half sm[];
    const int tid = threadIdx.x, wid = tid >> 5, lane = tid & 31;
    const int p0 = blockIdx.x * 256;
    const int y = blockIdx.y;
    const int isK = y >> 1;
    const int e0 = (y & 1) * 128;
    const int b = blockIdx.z;

    const int ew = (wid >> 2) * 64;
    const int pw = (wid & 3) * 64;

    float acc[4][8][4];
#pragma unroll
    for (int mt = 0; mt < 4; ++mt)
#pragma unroll
        for (int nt = 0; nt < 8; ++nt)
#pragma unroll
            for (int i = 0; i < 4; ++i) acc[mt][nt][i] = 0.f;

    // prefetch all 4 K-stages
    gemm_load_stage(sm,                   0, tid, isK, e0, b, p0);
    gemm_load_stage(sm + STAGE_ELEMS,     1, tid, isK, e0, b, p0);
    gemm_load_stage(sm + 2 * STAGE_ELEMS, 2, tid, isK, e0, b, p0);
    gemm_load_stage(sm + 3 * STAGE_ELEMS, 3, tid, isK, e0, b, p0);

#pragma unroll 1
    for (int s = 0; s < 4; ++s) {
        if (s == 0)      { CP_WAITN(3); }
        else if (s == 1) { CP_WAITN(2); }
        else if (s == 2) { CP_WAITN(1); }
        else             { CP_WAITN(0); }
        __syncthreads();

        __half* As = sm + s * STAGE_ELEMS;
        __half* Bs = As + A_STAGE;

#pragma unroll
        for (int ks = 0; ks < 4; ++ks) {
            const int k16 = ks * 16;
            uint32_t a[4][4];
#pragma unroll
            for (int mt = 0; mt < 4; ++mt) {
                uint32_t ad = smem_u32(&As[(ew + mt * 16 + (lane & 15)) * AROW
                                           + k16 + (lane >> 4) * 8]);
                LDSM_X4(a[mt][0], a[mt][1], a[mt][2], a[mt][3], ad);
            }
#pragma unroll
            for (int n2 = 0; n2 < 4; ++n2) {
                uint32_t bf[4];
                uint32_t bd = smem_u32(&Bs[(k16 + (lane & 15)) * BROW
                                           + pw + n2 * 16 + (lane >> 4) * 8]);
                LDSM_X4_T(bf[0], bf[1], bf[2], bf[3], bd);
#pragma unroll
                for (int mt = 0; mt < 4; ++mt) {
                    MMA16816(acc[mt][n2*2][0], acc[mt][n2*2][1],
                             acc[mt][n2*2][2], acc[mt][n2*2][3],
                             a[mt][0], a[mt][1], a[mt][2], a[mt][3],
                             bf[0], bf[1]);
                    MMA16816(acc[mt][n2*2+1][0], acc[mt][n2*2+1][1],
                             acc[mt][n2*2+1][2], acc[mt][n2*2+1][3],
                             a[mt][0], a[mt][1], a[mt][2], a[mt][3],
                             bf[2], bf[3]);
                }
            }
        }
    }

    float* Out = (isK ? g_k4 : g_q) + (size_t)b * (DKC * PC);
#pragma unroll
    for (int mt = 0; mt < 4; ++mt) {
#pragma unroll
        for (int nt = 0; nt < 8; ++nt) {
            const int r = e0 + ew + mt * 16 + (lane >> 2);
            const int c = p0 + pw + nt * 8 + (lane & 3) * 2;
            *(float2*)&Out[(size_t)r * PC + c] =
                make_float2(acc[mt][nt][0], acc[mt][nt][1]);
            *(float2*)&Out[(size_t)(r + 8) * PC + c] =
                make_float2(acc[mt][nt][2], acc[mt][nt][3]);
        }
    }
}

// ---------------------------------------------------------------------------
// v projection: thread = (e-group of 4, b, p)
// ---------------------------------------------------------------------------
__global__ __launch_bounds__(256) void proj_v_kernel(
    const float* __restrict__ fm, const float* __restrict__ Vw)
{
    __shared__ float Vs[DVC][DVC];
    const int tid = threadIdx.x;
    for (int i = tid; i < DVC * DVC; i += 256) Vs[i >> 5][i & 31] = Vw[i];
    __syncthreads();

    const int gid = blockIdx.x * 256 + tid;   // 131072 threads
    const int eg = gid >> 14;                  // 0..7
    const int b = (gid >> 12) & 3;
    const int p = gid & (PC - 1);

    float f[DVC];
    const float* fmp = fm + (size_t)b * DVC * PC + p;
#pragma unroll
    for (int d = 0; d < DVC; ++d) f[d] = fmp[(size_t)d * PC];

    float* vo = g_v4 + (size_t)b * DVC * PC + p;
#pragma unroll
    for (int ee = 0; ee < 4; ++ee) {
        const int e = eg * 4 + ee;
        float a = 0.f;
#pragma unroll
        for (int d = 0; d < DVC; ++d) a += f[d] * Vs[d][e];
        vo[(size_t)e * PC] = a;
    }
}

// ---------------------------------------------------------------------------
// scores + softmax fused, q staged in smem.
// grid (64 h, 4 m-quartets), 256 threads = (w 64, mg 4); each mg: 2 m, 4 b.
// ---------------------------------------------------------------------------
__global__ __launch_bounds__(256) void scores_softmax_kernel(
    const float* __restrict__ kbuf, float scale)
{
    __shared__ float qs[32 * 4 * 64];    // [d'][b][w]  32KB
    __shared__ float sS[4 * 8 * 64];     // [b][m][w]    8KB
    __shared__ float sMx[32], sInv[32];

    const int tid = threadIdx.x;
    const int h = blockIdx.x;
    const int mq = blockIdx.y;
    const int w = tid & 63;
    const int mg = tid >> 6;
    const int p = h * 64 + w;
    const int m0 = mq * 8 + mg * 2;

    const float* kp[2];
#pragma unroll
    for (int j = 0; j < 2; ++j) {
        const int m = m0 + j;
        kp[j] = ((m < BC) ? g_k4 + (size_t)m * (DKC * PC)
                          : kbuf + (size_t)(m - BC) * (DKC * PC)) + p;
    }

    float S[4][2];
#pragma unroll
    for (int bb = 0; bb < 4; ++bb) { S[bb][0] = 0.f; S[bb][1] = 0.f; }

    for (int dc = 0; dc < 8; ++dc) {
        __syncthreads();
#pragma unroll
        for (int i = 0; i < 8; ++i) {
            const int flat = (i * 256 + tid) * 4;
            const int d_ = flat >> 8, bb = (flat >> 6) & 3, w0 = flat & 63;
            *(float4*)&qs[flat] = *(const float4*)&g_q[
                ((size_t)(bb * DKC + dc * 32 + d_)) * PC + h * 64 + w0];
        }
        __syncthreads();
#pragma unroll 4
        for (int d_ = 0; d_ < 32; ++d_) {
            const float kv0 = kp[0][(size_t)(dc * 32 + d_) * PC];
            const float kv1 = kp[1][(size_t)(dc * 32 + d_) * PC];
#pragma unroll
            for (int bb = 0; bb < 4; ++bb) {
                const float qv = qs[(d_ * 4 + bb) * 64 + w];
                S[bb][0] += qv * kv0;
                S[bb][1] += qv * kv1;
            }
        }
    }

#pragma unroll
    for (int bb = 0; bb < 4; ++bb)
#pragma unroll
        for (int j = 0; j < 2; ++j)
            sS[(bb * 8 + mg * 2 + j) * 64 + w] = S[bb][j] * scale;
    __syncthreads();

    {
        const int g = tid >> 3, jj = tid & 7;   // 32 groups x 8 threads
        float v[8];
        float mx = -1e30f;
#pragma unroll
        for (int i = 0; i < 8; ++i) { v[i] = sS[g * 64 + jj * 8 + i]; mx = fmaxf(mx, v[i]); }
        mx = fmaxf(mx, __shfl_xor_sync(0xffffffffu, mx, 1));
        mx = fmaxf(mx, __shfl_xor_sync(0xffffffffu, mx, 2));
        mx = fmaxf(mx, __shfl_xor_sync(0xffffffffu, mx, 4));
        float sm = 0.f;
#pragma unroll
        for (int i = 0; i < 8; ++i) sm += __expf(v[i] - mx);
        sm += __shfl_xor_sync(0xffffffffu, sm, 1);
        sm += __shfl_xor_sync(0xffffffffu, sm, 2);
        sm += __shfl_xor_sync(0xffffffffu, sm, 4);
        if (jj == 0) { sMx[g] = mx; sInv[g] = 1.f / sm; }
    }
    __syncthreads();

#pragma unroll
    for (int bb = 0; bb < 4; ++bb)
#pragma unroll
        for (int j = 0; j < 2; ++j) {
            const int g = bb * 8 + mg * 2 + j;
            const float a = __expf(S[bb][j] * scale - sMx[g]) * sInv[g];
            g_attn[((size_t)bb * MC + m0 + j) * PC + p] = a;
        }
}

// ---------------------------------------------------------------------------
// ctx + blend
// ---------------------------------------------------------------------------
__global__ __launch_bounds__(256) void ctx_out_kernel(
    const float* __restrict__ vbuf, const float* __restrict__ fm,
    float* __restrict__ out)
{
    const int gid = blockIdx.x * 256 + threadIdx.x;
    const int d = gid >> 12;
    const int p = gid & (PC - 1);

    float c[4] = {0.f, 0.f, 0.f, 0.f};
    const float* ap = g_attn + p;

#pragma unroll 4
    for (int m = 0; m < MC; ++m) {
        const float* vsrc = (m < BC) ? (g_v4 + (size_t)m * DVC * PC)
                                     : (vbuf + (size_t)(m - BC) * DVC * PC);
        const float vv = vsrc[(size_t)d * PC + p];
#pragma unroll
        for (int bb = 0; bb < 4; ++bb)
            c[bb] += ap[(size_t)(bb * MC + m) * PC] * vv;
    }

#pragma unroll
    for (int bb = 0; bb < 4; ++bb) {
        const size_t o = ((size_t)bb * DVC + d) * PC + p;
        out[o] = fm[o] + 0.5f * c[bb];
    }
}

// ---------------------------------------------------------------------------
extern "C" void kernel_launch(void* const* d_in, const int* in_sizes, int n_in,
                              void* d_out, int out_size)
{
    (void)in_sizes; (void)n_in; (void)out_size;
    const float* fc = (const float*)d_in[0];
    const float* fm = (const float*)d_in[1];
    const float* kb = (const float*)d_in[2];
    const float* vb = (const float*)d_in[3];
    const float* Qw = (const float*)d_in[4];
    const float* Kw = (const float*)d_in[5];
    const float* Vw = (const float*)d_in[6];
    float* out = (float*)d_out;

    const float scale = (float)(log(135168.0) / log(1000.0) / 16.0);

    cudaFuncSetAttribute(gemm_hmma_kernel,
                         cudaFuncAttributeMaxDynamicSharedMemorySize,
                         GEMM_SMEM_BYTES);

    convert_w_kernel<<<256, 256>>>(Qw, Kw);
    convert_fc_kernel<<<4096, 256>>>(fc);
    gemm_hmma_kernel<<<dim3(16, 4, 4), 256, GEMM_SMEM_BYTES>>>();
    proj_v_kernel<<<512, 256>>>(fm, Vw);
    scores_softmax_kernel<<<dim3(64, 4), 256>>>(kb, scale);
    ctx_out_kernel<<<512, 256>>>(vb, fm, out);
}